// round 9
// baseline (speedup 1.0000x reference)
#include <cuda_runtime.h>

// ---------------------------------------------------------------------------
// FCOS loss, 5 FPN levels, B=16, C=80 — single kernel, cheap completion.
// Blocks [0,PIXBLK): sparse positive-pixel work.
// Blocks [PIXBLK,TOTAL): stream conf for the focal negative term using a
//   double-buffered 8-subtile pipeline (256KB per block) so loads stay
//   outstanding ~100% of block lifetime and oe*MLP_p1 stays near the
//   L1tex-queue threshold (kills the multi-CTA spread).
// Completion: only the atomic-issuing warp fences; last-arriving block
// finalizes the scalar and resets all state (replay-deterministic).
// ---------------------------------------------------------------------------

#define NB 16          // batch
#define NC 80          // classes

// per-level HW
#define HW0 12800
#define HW1 3200
#define HW2 800
#define HW3 208
#define HW4 56

// per-level C*H*W in float4 units (C*HW/4)
#define CHWV0 256000
#define CHWV1 64000
#define CHWV2 16000
#define CHWV3 4160
#define CHWV4 1120

// focal tiling: 8 subtiles x (256 threads x 8 float4) = 16384 vec4 per block
#define SUBV 2048              // vec4 per subtile
#define SPANV (8*SUBV)         // 16384 vec4 per block
#define NBX0 16   // ceil(256000/16384)
#define NBX1 4    // ceil(64000/16384)
#define NBX2 1
#define NBX3 1
#define NBX4 1
#define XB1 (NBX0)             // 16
#define XB2 (XB1+NBX1)         // 20
#define XB3 (XB2+NBX2)         // 21
#define XB4 (XB3+NBX3)         // 22
#define NBLKX (XB4+NBX4)       // 23 focal blocks per image
#define FBLK (NBLKX*NB)        // 368 focal blocks

// pixel work: pixels per level across batch (B*HW), cumulative
#define P0 (NB*HW0)                // 204800
#define P1 (P0 + NB*HW1)           // 256000
#define P2 (P1 + NB*HW2)           // 268800
#define P3 (P2 + NB*HW3)           // 272128
#define P4 (P3 + NB*HW4)           // 273024
#define PIXBLK ((P4 + 255) / 256)  // 1067
#define TOTALBLK (FBLK + PIXBLK)   // 1435

// 0.75 * ln(2): folds -(1-ALPHA) and the log2->ln conversion
#define NEG_SCALE (-0.519860385f)

// accumulators (device globals: zero at load, reset to zero by last block)
__device__ float    g_conf[NB];
__device__ float    g_loc[NB];
__device__ float    g_ctr[NB];
__device__ int      g_npos[NB];
__device__ unsigned g_count;

__device__ __forceinline__ float clipp(float p) {
    return fminf(fmaxf(p, 1e-8f), 0.99999999f);
}

// Load one 8-vec4 batch; OOB lanes zero-filled (zero contributes 0 to the sum).
template<bool FULL>
__device__ __forceinline__ void load_tile(float4 (&buf)[8], const float4* __restrict__ cp,
                                          int off, int chwv) {
    #pragma unroll
    for (int k = 0; k < 8; k++) {
        int v = off + k * 256;
        if (FULL || v < chwv) buf[k] = __ldg(cp + v);
        else                  buf[k] = make_float4(0.f, 0.f, 0.f, 0.f);
    }
}

__device__ __forceinline__ float tile_acc(const float4 (&buf)[8]) {
    float acc = 0.0f;
    #pragma unroll
    for (int k = 0; k < 8; k++) {
        float4 p = buf[k];
        acc += p.x * p.x * __log2f(1.0f - p.x)
             + p.y * p.y * __log2f(1.0f - p.y)
             + p.z * p.z * __log2f(1.0f - p.z)
             + p.w * p.w * __log2f(1.0f - p.w);
    }
    return acc;
}

// Double-buffered pipeline over 8 subtiles: loads for s+1 issue before the
// compute of s, so memory stays busy throughout.
template<bool FULL>
__device__ __forceinline__ float focal_span(const float4* __restrict__ cp,
                                            int base, int chwv) {
    float4 buf[2][8];
    float acc = 0.0f;
    load_tile<FULL>(buf[0], cp, base, chwv);
    #pragma unroll
    for (int s = 0; s < 8; s++) {
        if (s < 7) load_tile<FULL>(buf[(s + 1) & 1], cp, base + (s + 1) * SUBV, chwv);
        acc += tile_acc(buf[s & 1]);
    }
    return acc;
}

// ---------------------------------------------------------------------------
__global__ __launch_bounds__(256, 2) void fcos_work_kernel(
    const float* __restrict__ c0, const float* __restrict__ c1,
    const float* __restrict__ c2, const float* __restrict__ c3,
    const float* __restrict__ c4,
    const float* __restrict__ l0, const float* __restrict__ l1,
    const float* __restrict__ l2, const float* __restrict__ l3,
    const float* __restrict__ l4,
    const float* __restrict__ ce0, const float* __restrict__ ce1,
    const float* __restrict__ ce2, const float* __restrict__ ce3,
    const float* __restrict__ ce4,
    const float* __restrict__ t0, const float* __restrict__ t1,
    const float* __restrict__ t2, const float* __restrict__ t3,
    const float* __restrict__ t4,
    const int* __restrict__ k0, const int* __restrict__ k1,
    const int* __restrict__ k2, const int* __restrict__ k3,
    const int* __restrict__ k4,
    const int* __restrict__ m0, const int* __restrict__ m1,
    const int* __restrict__ m2, const int* __restrict__ m3,
    const int* __restrict__ m4,
    float* __restrict__ out)
{
    __shared__ int s_last;
    const int bid = blockIdx.x;
    const int tid = threadIdx.x;

    if (bid >= PIXBLK) {
        // ================= focal negative-term streaming =================
        const int fb = bid - PIXBLK;
        const int b  = fb / NBLKX;
        const int bx = fb - b * NBLKX;

        const float4* __restrict__ cp;
        int chwv, inner;
        if (bx < XB1)      { cp = (const float4*)c0; chwv = CHWV0; inner = bx;       }
        else if (bx < XB2) { cp = (const float4*)c1; chwv = CHWV1; inner = bx - XB1; }
        else if (bx < XB3) { cp = (const float4*)c2; chwv = CHWV2; inner = bx - XB2; }
        else if (bx < XB4) { cp = (const float4*)c3; chwv = CHWV3; inner = bx - XB3; }
        else               { cp = (const float4*)c4; chwv = CHWV4; inner = bx - XB4; }

        cp += (long)b * chwv;
        const int bstart = inner * SPANV;
        const int base   = bstart + tid;

        // acc accumulates p^2 * log2(1-p); scaled by -(0.75*ln2) at the end.
        // (No in-stream clipping: p in [0,1); effect of the clip is < 1e-16.)
        float acc;
        if (bstart + SPANV <= chwv) acc = focal_span<true >(cp, base, chwv);
        else                        acc = focal_span<false>(cp, base, chwv);
        acc *= NEG_SCALE;

        #pragma unroll
        for (int o = 16; o > 0; o >>= 1)
            acc += __shfl_down_sync(0xffffffffu, acc, o);
        __shared__ float sred[8];
        const int lane = tid & 31, wid = tid >> 5;
        if (lane == 0) sred[wid] = acc;
        __syncthreads();
        if (tid < 8) {
            float v = sred[tid];
            #pragma unroll
            for (int o = 4; o > 0; o >>= 1)
                v += __shfl_down_sync(0xffu, v, o);
            if (tid == 0) {
                atomicAdd(&g_conf[b], v);
                __threadfence();   // release my contribution (1 thread/block)
            }
        }
    } else {
        // ================= sparse positive-pixel work =================
        __shared__ float s_conf[NB], s_loc[NB], s_ctr[NB];
        __shared__ int   s_np[NB];
        if (tid < NB) {
            s_conf[tid] = 0.0f; s_loc[tid] = 0.0f; s_ctr[tid] = 0.0f; s_np[tid] = 0;
        }
        __syncthreads();

        const int id = bid * 256 + tid;
        if (id < P4) {
            const float *conf, *loc, *ctr, *ltrb;
            const int *cls, *pos;
            int HW, i;
            if (id < P0)      { conf=c0; loc=l0; ctr=ce0; ltrb=t0; cls=k0; pos=m0; HW=HW0; i=id;    }
            else if (id < P1) { conf=c1; loc=l1; ctr=ce1; ltrb=t1; cls=k1; pos=m1; HW=HW1; i=id-P0; }
            else if (id < P2) { conf=c2; loc=l2; ctr=ce2; ltrb=t2; cls=k2; pos=m2; HW=HW2; i=id-P1; }
            else if (id < P3) { conf=c3; loc=l3; ctr=ce3; ltrb=t3; cls=k3; pos=m3; HW=HW3; i=id-P2; }
            else              { conf=c4; loc=l4; ctr=ce4; ltrb=t4; cls=k4; pos=m4; HW=HW4; i=id-P3; }

            const int b   = i / HW;
            const int pix = i - b * HW;
            const long pbase = (long)b * HW + pix;

            if (pos[pbase] == 0) {
                // focal correction at (b, cls, pix): pos - neg (full clipped form)
                const int c = cls[pbase];
                float p = clipp(conf[((long)b * NC + c) * HW + pix]);
                float q = 1.0f - p;
                float corr = -0.25f * q * q * __logf(p) + 0.75f * p * p * __logf(q);

                // IoU loss
                const long o = (long)b * 4 * HW + pix;
                float lp = loc[o]           * 32.0f;
                float tp = loc[o + HW]      * 32.0f;
                float rp = loc[o + 2 * HW]  * 32.0f;
                float bp = loc[o + 3 * HW]  * 32.0f;
                float lt = ltrb[o]          * 32.0f;
                float tt = ltrb[o + HW]     * 32.0f;
                float rt = ltrb[o + 2 * HW] * 32.0f;
                float bt = ltrb[o + 3 * HW] * 32.0f;

                float iw = fmaxf(fminf(lp, lt) + fminf(rp, rt), 0.0f);
                float ih = fmaxf(fminf(tp, tt) + fminf(bp, bt), 0.0f);
                float inter  = iw * ih;
                float area_p = fmaxf(lp + rp, 0.0f) * fmaxf(tp + bp, 0.0f);
                float area_t = (lt + rt) * (tt + bt);
                float iou = inter / (area_p + area_t - inter + 1e-6f);
                float loss_l = -__logf(iou + 1e-6f);

                // centerness BCE
                float ctr_t = sqrtf((fminf(lt, rt) / (fmaxf(lt, rt) + 1e-6f)) *
                                    (fminf(tt, bt) / (fmaxf(tt, bt) + 1e-6f)));
                float cp = ctr[pbase];
                cp = fminf(fmaxf(cp, 1e-8f), 1.0f - 1e-8f);
                float bce = -(ctr_t * __logf(cp) + (1.0f - ctr_t) * __logf(1.0f - cp));

                atomicAdd(&s_conf[b], corr);
                atomicAdd(&s_loc[b],  loss_l);
                atomicAdd(&s_ctr[b],  bce);
                atomicAdd(&s_np[b],   1);
            }
        }
        __syncthreads();

        if (tid < NB) {
            if (s_conf[tid] != 0.0f) atomicAdd(&g_conf[tid], s_conf[tid]);
            if (s_loc[tid]  != 0.0f) atomicAdd(&g_loc[tid],  s_loc[tid]);
            if (s_ctr[tid]  != 0.0f) atomicAdd(&g_ctr[tid],  s_ctr[tid]);
            if (s_np[tid])           atomicAdd(&g_npos[tid], s_np[tid]);
        }
        if ((tid >> 5) == 0)
            __threadfence();   // release: issuing warp only (1 MEMBAR/block)
    }

    // ============ completion: last-arriving block finalizes ============
    __syncthreads();
    if (tid == 0)
        s_last = (atomicAdd(&g_count, 1u) == (unsigned)(TOTALBLK - 1));
    __syncthreads();

    if (s_last && tid < 32) {
        __threadfence();   // acquire: all prior releases are now visible
        volatile float* vconf = g_conf;
        volatile float* vloc  = g_loc;
        volatile float* vctr  = g_ctr;
        volatile int*   vnp   = g_npos;

        float v = 0.0f;
        if (tid < NB) {
            float lc = vconf[tid], ll = vloc[tid], lctr = vctr[tid];
            int   np = vnp[tid];
            float pf = (float)np;
            v = (np > 0) ? (lctr + (lc + ll) / fmaxf(pf, 1.0f))
                         : (lctr + lc + ll);
        }
        #pragma unroll
        for (int o = 16; o > 0; o >>= 1)
            v += __shfl_down_sync(0xffffffffu, v, o);
        if (tid == 0) out[0] = v * (1.0f / (float)NB);

        // reset state for the next invocation / graph replay
        if (tid < NB) {
            vconf[tid] = 0.0f; vloc[tid] = 0.0f; vctr[tid] = 0.0f; vnp[tid] = 0;
        }
        __threadfence();
        if (tid == 0) g_count = 0u;
    }
}

// ---------------------------------------------------------------------------
extern "C" void kernel_launch(void* const* d_in, const int* in_sizes, int n_in,
                              void* d_out, int out_size)
{
    (void)n_in; (void)out_size;

    // Runtime input-order detection.
    // Per-level order:    in_sizes[1] = 16*4*12800 = 819200   (loc0)
    // Type-grouped order: in_sizes[1] = 16*80*3200 = 4096000  (conf1)
    int iconf[5], iloc[5], ictr[5], iltrb[5], icls[5], ipos[5];
    if (in_sizes[1] == 16 * 4 * 12800) {
        for (int l = 0; l < 5; l++) {
            iconf[l] = 6 * l + 0; iloc[l] = 6 * l + 1; ictr[l] = 6 * l + 2;
            iltrb[l] = 6 * l + 3; icls[l] = 6 * l + 4; ipos[l] = 6 * l + 5;
        }
    } else {
        for (int l = 0; l < 5; l++) {
            iconf[l] = l; iloc[l] = 5 + l; ictr[l] = 10 + l;
            iltrb[l] = 15 + l; icls[l] = 20 + l; ipos[l] = 25 + l;
        }
    }

    fcos_work_kernel<<<TOTALBLK, 256>>>(
        (const float*)d_in[iconf[0]], (const float*)d_in[iconf[1]],
        (const float*)d_in[iconf[2]], (const float*)d_in[iconf[3]],
        (const float*)d_in[iconf[4]],
        (const float*)d_in[iloc[0]],  (const float*)d_in[iloc[1]],
        (const float*)d_in[iloc[2]],  (const float*)d_in[iloc[3]],
        (const float*)d_in[iloc[4]],
        (const float*)d_in[ictr[0]],  (const float*)d_in[ictr[1]],
        (const float*)d_in[ictr[2]],  (const float*)d_in[ictr[3]],
        (const float*)d_in[ictr[4]],
        (const float*)d_in[iltrb[0]], (const float*)d_in[iltrb[1]],
        (const float*)d_in[iltrb[2]], (const float*)d_in[iltrb[3]],
        (const float*)d_in[iltrb[4]],
        (const int*)d_in[icls[0]], (const int*)d_in[icls[1]],
        (const int*)d_in[icls[2]], (const int*)d_in[icls[3]],
        (const int*)d_in[icls[4]],
        (const int*)d_in[ipos[0]], (const int*)d_in[ipos[1]],
        (const int*)d_in[ipos[2]], (const int*)d_in[ipos[3]],
        (const int*)d_in[ipos[4]],
        (float*)d_out);
}

// round 10
// speedup vs baseline: 1.2270x; 1.2270x over previous
#include <cuda_runtime.h>

// ---------------------------------------------------------------------------
// FCOS loss, 5 FPN levels, B=16, C=80 — single kernel, cheap completion.
// Blocks [0,PIXBLK): sparse positive-pixel work.
// Blocks [PIXBLK,TOTAL): stream conf, sum focal negative term.
//   Per-thread batch is 4 float4 (MLP_p1=4): per the B300 multi-CTA-spread
//   model, oe*MLP_p1 near Q_th keeps cross-CTA L1tex-queue contention (and
//   therefore per-CTA time spread) near the floor, unlike MLP_p1=8.
// Completion: only the atomic-issuing warp fences; last-arriving block
// finalizes the scalar and resets all state (replay-deterministic).
// ---------------------------------------------------------------------------

#define NB 16          // batch
#define NC 80          // classes

// per-level HW
#define HW0 12800
#define HW1 3200
#define HW2 800
#define HW3 208
#define HW4 56

// per-level C*H*W in float4 units (C*HW/4)
#define CHWV0 256000
#define CHWV1 64000
#define CHWV2 16000
#define CHWV3 4160
#define CHWV4 1120

// focal tiling: 256 threads x 4 float4 per thread = 1024 vec4 per block
#define BVEC 1024
#define BLK0 250   // ceil(256000/1024)
#define BLK1 63    // ceil(64000/1024)
#define BLK2 16    // ceil(16000/1024)
#define BLK3 5     // ceil(4160/1024)
#define BLK4 2     // ceil(1120/1024)
#define CB1 (BLK0)                 // 250
#define CB2 (CB1+BLK1)             // 313
#define CB3 (CB2+BLK2)             // 329
#define CB4 (CB3+BLK3)             // 334
#define NBLKX (CB4+BLK4)           // 336 per image
#define FBLK (NBLKX*NB)            // 5376 focal blocks

// pixel work: pixels per level across batch (B*HW), cumulative
#define P0 (NB*HW0)                // 204800
#define P1 (P0 + NB*HW1)           // 256000
#define P2 (P1 + NB*HW2)           // 268800
#define P3 (P2 + NB*HW3)           // 272128
#define P4 (P3 + NB*HW4)           // 273024
#define PIXBLK ((P4 + 255) / 256)  // 1067
#define TOTALBLK (FBLK + PIXBLK)   // 6443

// 0.75 * ln(2): folds -(1-ALPHA) and the log2->ln conversion
#define NEG_SCALE (-0.519860385f)

// accumulators (device globals: zero at load, reset to zero by last block)
__device__ float    g_conf[NB];
__device__ float    g_loc[NB];
__device__ float    g_ctr[NB];
__device__ int      g_npos[NB];
__device__ unsigned g_count;

__device__ __forceinline__ float clipp(float p) {
    return fminf(fmaxf(p, 1e-8f), 0.99999999f);
}

// ---------------------------------------------------------------------------
__global__ __launch_bounds__(256) void fcos_work_kernel(
    const float* __restrict__ c0, const float* __restrict__ c1,
    const float* __restrict__ c2, const float* __restrict__ c3,
    const float* __restrict__ c4,
    const float* __restrict__ l0, const float* __restrict__ l1,
    const float* __restrict__ l2, const float* __restrict__ l3,
    const float* __restrict__ l4,
    const float* __restrict__ ce0, const float* __restrict__ ce1,
    const float* __restrict__ ce2, const float* __restrict__ ce3,
    const float* __restrict__ ce4,
    const float* __restrict__ t0, const float* __restrict__ t1,
    const float* __restrict__ t2, const float* __restrict__ t3,
    const float* __restrict__ t4,
    const int* __restrict__ k0, const int* __restrict__ k1,
    const int* __restrict__ k2, const int* __restrict__ k3,
    const int* __restrict__ k4,
    const int* __restrict__ m0, const int* __restrict__ m1,
    const int* __restrict__ m2, const int* __restrict__ m3,
    const int* __restrict__ m4,
    float* __restrict__ out)
{
    __shared__ int s_last;
    const int bid = blockIdx.x;
    const int tid = threadIdx.x;

    if (bid >= PIXBLK) {
        // ================= focal negative-term streaming =================
        const int fb = bid - PIXBLK;
        const int b  = fb / NBLKX;
        const int bx = fb - b * NBLKX;

        const float4* __restrict__ cp;
        int chwv, inner;
        if (bx < CB1)      { cp = (const float4*)c0; chwv = CHWV0; inner = bx;       }
        else if (bx < CB2) { cp = (const float4*)c1; chwv = CHWV1; inner = bx - CB1; }
        else if (bx < CB3) { cp = (const float4*)c2; chwv = CHWV2; inner = bx - CB2; }
        else if (bx < CB4) { cp = (const float4*)c3; chwv = CHWV3; inner = bx - CB3; }
        else               { cp = (const float4*)c4; chwv = CHWV4; inner = bx - CB4; }

        cp += (long)b * chwv;
        const int base = inner * BVEC + tid;

        // acc accumulates p^2 * log2(1-p); scaled by -(0.75*ln2) at the end.
        // (No in-stream clipping: p in [0,1); effect of the clip is < 1e-16.)
        float acc = 0.0f;
        if (inner * BVEC + BVEC <= chwv) {
            // fast path: full tile — batch of 4 LDG.128 (MLP_p1 = 4)
            float4 r[4];
            #pragma unroll
            for (int k = 0; k < 4; k++) r[k] = __ldg(cp + base + k * 256);
            #pragma unroll
            for (int k = 0; k < 4; k++) {
                float4 p = r[k];
                acc += p.x * p.x * __log2f(1.0f - p.x)
                     + p.y * p.y * __log2f(1.0f - p.y)
                     + p.z * p.z * __log2f(1.0f - p.z)
                     + p.w * p.w * __log2f(1.0f - p.w);
            }
        } else {
            #pragma unroll
            for (int k = 0; k < 4; k++) {
                int v = base + k * 256;
                if (v < chwv) {
                    float4 p = __ldg(cp + v);
                    acc += p.x * p.x * __log2f(1.0f - p.x)
                         + p.y * p.y * __log2f(1.0f - p.y)
                         + p.z * p.z * __log2f(1.0f - p.z)
                         + p.w * p.w * __log2f(1.0f - p.w);
                }
            }
        }
        acc *= NEG_SCALE;

        #pragma unroll
        for (int o = 16; o > 0; o >>= 1)
            acc += __shfl_down_sync(0xffffffffu, acc, o);
        __shared__ float sred[8];
        const int lane = tid & 31, wid = tid >> 5;
        if (lane == 0) sred[wid] = acc;
        __syncthreads();
        if (tid < 8) {
            float v = sred[tid];
            #pragma unroll
            for (int o = 4; o > 0; o >>= 1)
                v += __shfl_down_sync(0xffu, v, o);
            if (tid == 0) {
                atomicAdd(&g_conf[b], v);
                __threadfence();   // release my contribution (1 thread/block)
            }
        }
    } else {
        // ================= sparse positive-pixel work =================
        __shared__ float s_conf[NB], s_loc[NB], s_ctr[NB];
        __shared__ int   s_np[NB];
        if (tid < NB) {
            s_conf[tid] = 0.0f; s_loc[tid] = 0.0f; s_ctr[tid] = 0.0f; s_np[tid] = 0;
        }
        __syncthreads();

        const int id = bid * 256 + tid;
        if (id < P4) {
            const float *conf, *loc, *ctr, *ltrb;
            const int *cls, *pos;
            int HW, i;
            if (id < P0)      { conf=c0; loc=l0; ctr=ce0; ltrb=t0; cls=k0; pos=m0; HW=HW0; i=id;    }
            else if (id < P1) { conf=c1; loc=l1; ctr=ce1; ltrb=t1; cls=k1; pos=m1; HW=HW1; i=id-P0; }
            else if (id < P2) { conf=c2; loc=l2; ctr=ce2; ltrb=t2; cls=k2; pos=m2; HW=HW2; i=id-P1; }
            else if (id < P3) { conf=c3; loc=l3; ctr=ce3; ltrb=t3; cls=k3; pos=m3; HW=HW3; i=id-P2; }
            else              { conf=c4; loc=l4; ctr=ce4; ltrb=t4; cls=k4; pos=m4; HW=HW4; i=id-P3; }

            const int b   = i / HW;
            const int pix = i - b * HW;
            const long pbase = (long)b * HW + pix;

            if (pos[pbase] == 0) {
                // focal correction at (b, cls, pix): pos - neg (full clipped form)
                const int c = cls[pbase];
                float p = clipp(conf[((long)b * NC + c) * HW + pix]);
                float q = 1.0f - p;
                float corr = -0.25f * q * q * __logf(p) + 0.75f * p * p * __logf(q);

                // IoU loss
                const long o = (long)b * 4 * HW + pix;
                float lp = loc[o]           * 32.0f;
                float tp = loc[o + HW]      * 32.0f;
                float rp = loc[o + 2 * HW]  * 32.0f;
                float bp = loc[o + 3 * HW]  * 32.0f;
                float lt = ltrb[o]          * 32.0f;
                float tt = ltrb[o + HW]     * 32.0f;
                float rt = ltrb[o + 2 * HW] * 32.0f;
                float bt = ltrb[o + 3 * HW] * 32.0f;

                float iw = fmaxf(fminf(lp, lt) + fminf(rp, rt), 0.0f);
                float ih = fmaxf(fminf(tp, tt) + fminf(bp, bt), 0.0f);
                float inter  = iw * ih;
                float area_p = fmaxf(lp + rp, 0.0f) * fmaxf(tp + bp, 0.0f);
                float area_t = (lt + rt) * (tt + bt);
                float iou = inter / (area_p + area_t - inter + 1e-6f);
                float loss_l = -__logf(iou + 1e-6f);

                // centerness BCE
                float ctr_t = sqrtf((fminf(lt, rt) / (fmaxf(lt, rt) + 1e-6f)) *
                                    (fminf(tt, bt) / (fmaxf(tt, bt) + 1e-6f)));
                float cp = ctr[pbase];
                cp = fminf(fmaxf(cp, 1e-8f), 1.0f - 1e-8f);
                float bce = -(ctr_t * __logf(cp) + (1.0f - ctr_t) * __logf(1.0f - cp));

                atomicAdd(&s_conf[b], corr);
                atomicAdd(&s_loc[b],  loss_l);
                atomicAdd(&s_ctr[b],  bce);
                atomicAdd(&s_np[b],   1);
            }
        }
        __syncthreads();

        if (tid < NB) {
            if (s_conf[tid] != 0.0f) atomicAdd(&g_conf[tid], s_conf[tid]);
            if (s_loc[tid]  != 0.0f) atomicAdd(&g_loc[tid],  s_loc[tid]);
            if (s_ctr[tid]  != 0.0f) atomicAdd(&g_ctr[tid],  s_ctr[tid]);
            if (s_np[tid])           atomicAdd(&g_npos[tid], s_np[tid]);
        }
        if ((tid >> 5) == 0)
            __threadfence();   // release: issuing warp only (1 MEMBAR/block)
    }

    // ============ completion: last-arriving block finalizes ============
    __syncthreads();
    if (tid == 0)
        s_last = (atomicAdd(&g_count, 1u) == (unsigned)(TOTALBLK - 1));
    __syncthreads();

    if (s_last && tid < 32) {
        __threadfence();   // acquire: all prior releases are now visible
        volatile float* vconf = g_conf;
        volatile float* vloc  = g_loc;
        volatile float* vctr  = g_ctr;
        volatile int*   vnp   = g_npos;

        float v = 0.0f;
        if (tid < NB) {
            float lc = vconf[tid], ll = vloc[tid], lctr = vctr[tid];
            int   np = vnp[tid];
            float pf = (float)np;
            v = (np > 0) ? (lctr + (lc + ll) / fmaxf(pf, 1.0f))
                         : (lctr + lc + ll);
        }
        #pragma unroll
        for (int o = 16; o > 0; o >>= 1)
            v += __shfl_down_sync(0xffffffffu, v, o);
        if (tid == 0) out[0] = v * (1.0f / (float)NB);

        // reset state for the next invocation / graph replay
        if (tid < NB) {
            vconf[tid] = 0.0f; vloc[tid] = 0.0f; vctr[tid] = 0.0f; vnp[tid] = 0;
        }
        __threadfence();
        if (tid == 0) g_count = 0u;
    }
}

// ---------------------------------------------------------------------------
extern "C" void kernel_launch(void* const* d_in, const int* in_sizes, int n_in,
                              void* d_out, int out_size)
{
    (void)n_in; (void)out_size;

    // Runtime input-order detection.
    // Per-level order:    in_sizes[1] = 16*4*12800 = 819200   (loc0)
    // Type-grouped order: in_sizes[1] = 16*80*3200 = 4096000  (conf1)
    int iconf[5], iloc[5], ictr[5], iltrb[5], icls[5], ipos[5];
    if (in_sizes[1] == 16 * 4 * 12800) {
        for (int l = 0; l < 5; l++) {
            iconf[l] = 6 * l + 0; iloc[l] = 6 * l + 1; ictr[l] = 6 * l + 2;
            iltrb[l] = 6 * l + 3; icls[l] = 6 * l + 4; ipos[l] = 6 * l + 5;
        }
    } else {
        for (int l = 0; l < 5; l++) {
            iconf[l] = l; iloc[l] = 5 + l; ictr[l] = 10 + l;
            iltrb[l] = 15 + l; icls[l] = 20 + l; ipos[l] = 25 + l;
        }
    }

    fcos_work_kernel<<<TOTALBLK, 256>>>(
        (const float*)d_in[iconf[0]], (const float*)d_in[iconf[1]],
        (const float*)d_in[iconf[2]], (const float*)d_in[iconf[3]],
        (const float*)d_in[iconf[4]],
        (const float*)d_in[iloc[0]],  (const float*)d_in[iloc[1]],
        (const float*)d_in[iloc[2]],  (const float*)d_in[iloc[3]],
        (const float*)d_in[iloc[4]],
        (const float*)d_in[ictr[0]],  (const float*)d_in[ictr[1]],
        (const float*)d_in[ictr[2]],  (const float*)d_in[ictr[3]],
        (const float*)d_in[ictr[4]],
        (const float*)d_in[iltrb[0]], (const float*)d_in[iltrb[1]],
        (const float*)d_in[iltrb[2]], (const float*)d_in[iltrb[3]],
        (const float*)d_in[iltrb[4]],
        (const int*)d_in[icls[0]], (const int*)d_in[icls[1]],
        (const int*)d_in[icls[2]], (const int*)d_in[icls[3]],
        (const int*)d_in[icls[4]],
        (const int*)d_in[ipos[0]], (const int*)d_in[ipos[1]],
        (const int*)d_in[ipos[2]], (const int*)d_in[ipos[3]],
        (const int*)d_in[ipos[4]],
        (float*)d_out);
}

// round 12
// speedup vs baseline: 1.4488x; 1.1807x over previous
#include <cuda_runtime.h>

// ---------------------------------------------------------------------------
// FCOS loss, 5 FPN levels, B=16, C=80 — one persistent grid-stride kernel.
// Work units: [0, FBLK) focal conf-streaming tiles (256 thr x 4 float4),
//             [FBLK, TOTALU) sparse positive-pixel tiles (256 pixels).
// GRID=1184 persistent CTAs (8/SM @ 32 regs) loop over units; per-image
// partial sums live in smem for the CTA's whole lifetime and are flushed to
// __device__ globals ONCE per CTA. Last CTA to arrive finalizes the scalar
// and resets all state (replay-deterministic).
// ---------------------------------------------------------------------------

#define NB 16          // batch
#define NC 80          // classes

// per-level HW
#define HW0 12800
#define HW1 3200
#define HW2 800
#define HW3 208
#define HW4 56

// per-level C*H*W in float4 units (C*HW/4)
#define CHWV0 256000
#define CHWV1 64000
#define CHWV2 16000
#define CHWV3 4160
#define CHWV4 1120

// focal tiling: 256 threads x 4 float4 per thread = 1024 vec4 per tile
#define BVEC 1024
#define BLK0 250   // ceil(256000/1024)
#define BLK1 63
#define BLK2 16
#define BLK3 5
#define BLK4 2
#define CB1 (BLK0)                 // 250
#define CB2 (CB1+BLK1)             // 313
#define CB3 (CB2+BLK2)             // 329
#define CB4 (CB3+BLK3)             // 334
#define NBLKX (CB4+BLK4)           // 336 per image
#define FBLK (NBLKX*NB)            // 5376 focal tiles

// pixel work: pixels per level across batch (B*HW), cumulative
#define P0 (NB*HW0)                // 204800
#define P1 (P0 + NB*HW1)           // 256000
#define P2 (P1 + NB*HW2)           // 268800
#define P3 (P2 + NB*HW3)           // 272128
#define P4 (P3 + NB*HW4)           // 273024
#define PIXU ((P4 + 255) / 256)    // 1067 pixel units
#define TOTALU (FBLK + PIXU)       // 6443 work units

#define GRID 1184                  // 148 SMs x 8 CTAs (persistent)

// 0.75 * ln(2): folds -(1-ALPHA) and the log2->ln conversion
#define NEG_SCALE (-0.519860385f)

// accumulators (device globals: zero at load, reset to zero by last CTA)
__device__ float    g_conf[NB];
__device__ float    g_loc[NB];
__device__ float    g_ctr[NB];
__device__ int      g_npos[NB];
__device__ unsigned g_count;

__device__ __forceinline__ float clipp(float p) {
    return fminf(fmaxf(p, 1e-8f), 0.99999999f);
}

// ---------------------------------------------------------------------------
__global__ __launch_bounds__(256) void fcos_work_kernel(
    const float* __restrict__ c0, const float* __restrict__ c1,
    const float* __restrict__ c2, const float* __restrict__ c3,
    const float* __restrict__ c4,
    const float* __restrict__ l0, const float* __restrict__ l1,
    const float* __restrict__ l2, const float* __restrict__ l3,
    const float* __restrict__ l4,
    const float* __restrict__ ce0, const float* __restrict__ ce1,
    const float* __restrict__ ce2, const float* __restrict__ ce3,
    const float* __restrict__ ce4,
    const float* __restrict__ t0, const float* __restrict__ t1,
    const float* __restrict__ t2, const float* __restrict__ t3,
    const float* __restrict__ t4,
    const int* __restrict__ k0, const int* __restrict__ k1,
    const int* __restrict__ k2, const int* __restrict__ k3,
    const int* __restrict__ k4,
    const int* __restrict__ m0, const int* __restrict__ m1,
    const int* __restrict__ m2, const int* __restrict__ m3,
    const int* __restrict__ m4,
    float* __restrict__ out)
{
    __shared__ float s_conf[NB], s_loc[NB], s_ctr[NB];
    __shared__ int   s_np[NB];
    __shared__ int   s_last;

    const int tid  = threadIdx.x;
    const int lane = tid & 31;

    if (tid < NB) {
        s_conf[tid] = 0.0f; s_loc[tid] = 0.0f; s_ctr[tid] = 0.0f; s_np[tid] = 0;
    }
    __syncthreads();

    for (int unit = blockIdx.x; unit < TOTALU; unit += GRID) {
        if (unit < FBLK) {
            // ============== focal negative-term streaming tile ==============
            const int b  = unit / NBLKX;
            const int bx = unit - b * NBLKX;

            const float4* __restrict__ cp;
            int chwv, inner;
            if (bx < CB1)      { cp = (const float4*)c0; chwv = CHWV0; inner = bx;       }
            else if (bx < CB2) { cp = (const float4*)c1; chwv = CHWV1; inner = bx - CB1; }
            else if (bx < CB3) { cp = (const float4*)c2; chwv = CHWV2; inner = bx - CB2; }
            else if (bx < CB4) { cp = (const float4*)c3; chwv = CHWV3; inner = bx - CB3; }
            else               { cp = (const float4*)c4; chwv = CHWV4; inner = bx - CB4; }

            cp += (long)b * chwv;
            const int base = inner * BVEC + tid;

            // acc accumulates p^2 * log2(1-p); scaled by -(0.75*ln2) at flush.
            // (No in-stream clipping: p in [0,1); clip effect < 1e-16.)
            float acc = 0.0f;
            if (inner * BVEC + BVEC <= chwv) {
                float4 r[4];
                #pragma unroll
                for (int k = 0; k < 4; k++) r[k] = __ldg(cp + base + k * 256);
                #pragma unroll
                for (int k = 0; k < 4; k++) {
                    float4 p = r[k];
                    acc += p.x * p.x * __log2f(1.0f - p.x)
                         + p.y * p.y * __log2f(1.0f - p.y)
                         + p.z * p.z * __log2f(1.0f - p.z)
                         + p.w * p.w * __log2f(1.0f - p.w);
                }
            } else {
                #pragma unroll
                for (int k = 0; k < 4; k++) {
                    int v = base + k * 256;
                    if (v < chwv) {
                        float4 p = __ldg(cp + v);
                        acc += p.x * p.x * __log2f(1.0f - p.x)
                             + p.y * p.y * __log2f(1.0f - p.y)
                             + p.z * p.z * __log2f(1.0f - p.z)
                             + p.w * p.w * __log2f(1.0f - p.w);
                    }
                }
            }

            // warp-level reduce, then one smem atomic per warp (no barrier)
            #pragma unroll
            for (int o = 16; o > 0; o >>= 1)
                acc += __shfl_down_sync(0xffffffffu, acc, o);
            if (lane == 0)
                atomicAdd(&s_conf[b], acc * NEG_SCALE);
        } else {
            // ================= sparse positive-pixel unit =================
            const int id = (unit - FBLK) * 256 + tid;
            if (id < P4) {
                const float *conf, *loc, *ctr, *ltrb;
                const int *cls, *pos;
                int HW, i;
                if (id < P0)      { conf=c0; loc=l0; ctr=ce0; ltrb=t0; cls=k0; pos=m0; HW=HW0; i=id;    }
                else if (id < P1) { conf=c1; loc=l1; ctr=ce1; ltrb=t1; cls=k1; pos=m1; HW=HW1; i=id-P0; }
                else if (id < P2) { conf=c2; loc=l2; ctr=ce2; ltrb=t2; cls=k2; pos=m2; HW=HW2; i=id-P1; }
                else if (id < P3) { conf=c3; loc=l3; ctr=ce3; ltrb=t3; cls=k3; pos=m3; HW=HW3; i=id-P2; }
                else              { conf=c4; loc=l4; ctr=ce4; ltrb=t4; cls=k4; pos=m4; HW=HW4; i=id-P3; }

                const int b   = i / HW;
                const int pix = i - b * HW;
                const long pbase = (long)b * HW + pix;

                if (pos[pbase] == 0) {
                    // focal correction at (b, cls, pix): pos - neg
                    const int c = cls[pbase];
                    float p = clipp(conf[((long)b * NC + c) * HW + pix]);
                    float q = 1.0f - p;
                    float corr = -0.25f * q * q * __logf(p) + 0.75f * p * p * __logf(q);

                    // IoU loss
                    const long o = (long)b * 4 * HW + pix;
                    float lp = loc[o]           * 32.0f;
                    float tp = loc[o + HW]      * 32.0f;
                    float rp = loc[o + 2 * HW]  * 32.0f;
                    float bp = loc[o + 3 * HW]  * 32.0f;
                    float lt = ltrb[o]          * 32.0f;
                    float tt = ltrb[o + HW]     * 32.0f;
                    float rt = ltrb[o + 2 * HW] * 32.0f;
                    float bt = ltrb[o + 3 * HW] * 32.0f;

                    float iw = fmaxf(fminf(lp, lt) + fminf(rp, rt), 0.0f);
                    float ih = fmaxf(fminf(tp, tt) + fminf(bp, bt), 0.0f);
                    float inter  = iw * ih;
                    float area_p = fmaxf(lp + rp, 0.0f) * fmaxf(tp + bp, 0.0f);
                    float area_t = (lt + rt) * (tt + bt);
                    float iou = inter / (area_p + area_t - inter + 1e-6f);
                    float loss_l = -__logf(iou + 1e-6f);

                    // centerness BCE
                    float ctr_t = sqrtf((fminf(lt, rt) / (fmaxf(lt, rt) + 1e-6f)) *
                                        (fminf(tt, bt) / (fmaxf(tt, bt) + 1e-6f)));
                    float cp2 = ctr[pbase];
                    cp2 = fminf(fmaxf(cp2, 1e-8f), 1.0f - 1e-8f);
                    float bce = -(ctr_t * __logf(cp2) + (1.0f - ctr_t) * __logf(1.0f - cp2));

                    atomicAdd(&s_conf[b], corr);
                    atomicAdd(&s_loc[b],  loss_l);
                    atomicAdd(&s_ctr[b],  bce);
                    atomicAdd(&s_np[b],   1);
                }
            }
        }
    }

    // ============ flush CTA partials once, then completion ============
    __syncthreads();
    if (tid < NB) {
        if (s_conf[tid] != 0.0f) atomicAdd(&g_conf[tid], s_conf[tid]);
        if (s_loc[tid]  != 0.0f) atomicAdd(&g_loc[tid],  s_loc[tid]);
        if (s_ctr[tid]  != 0.0f) atomicAdd(&g_ctr[tid],  s_ctr[tid]);
        if (s_np[tid])           atomicAdd(&g_npos[tid], s_np[tid]);
    }
    if ((tid >> 5) == 0)
        __threadfence();   // release: flushing warp only (1 MEMBAR/CTA)
    __syncthreads();
    if (tid == 0)
        s_last = (atomicAdd(&g_count, 1u) == (unsigned)(GRID - 1));
    __syncthreads();

    if (s_last && tid < 32) {
        __threadfence();   // acquire: all prior releases are now visible
        volatile float* vconf = g_conf;
        volatile float* vloc  = g_loc;
        volatile float* vctr  = g_ctr;
        volatile int*   vnp   = g_npos;

        float v = 0.0f;
        if (tid < NB) {
            float lc = vconf[tid], ll = vloc[tid], lctr = vctr[tid];
            int   np = vnp[tid];
            float pf = (float)np;
            v = (np > 0) ? (lctr + (lc + ll) / fmaxf(pf, 1.0f))
                         : (lctr + lc + ll);
        }
        #pragma unroll
        for (int o = 16; o > 0; o >>= 1)
            v += __shfl_down_sync(0xffffffffu, v, o);
        if (tid == 0) out[0] = v * (1.0f / (float)NB);

        // reset state for the next invocation / graph replay
        if (tid < NB) {
            vconf[tid] = 0.0f; vloc[tid] = 0.0f; vctr[tid] = 0.0f; vnp[tid] = 0;
        }
        __threadfence();
        if (tid == 0) g_count = 0u;
    }
}

// ---------------------------------------------------------------------------
extern "C" void kernel_launch(void* const* d_in, const int* in_sizes, int n_in,
                              void* d_out, int out_size)
{
    (void)n_in; (void)out_size;

    // Runtime input-order detection.
    // Per-level order:    in_sizes[1] = 16*4*12800 = 819200   (loc0)
    // Type-grouped order: in_sizes[1] = 16*80*3200 = 4096000  (conf1)
    int iconf[5], iloc[5], ictr[5], iltrb[5], icls[5], ipos[5];
    if (in_sizes[1] == 16 * 4 * 12800) {
        for (int l = 0; l < 5; l++) {
            iconf[l] = 6 * l + 0; iloc[l] = 6 * l + 1; ictr[l] = 6 * l + 2;
            iltrb[l] = 6 * l + 3; icls[l] = 6 * l + 4; ipos[l] = 6 * l + 5;
        }
    } else {
        for (int l = 0; l < 5; l++) {
            iconf[l] = l; iloc[l] = 5 + l; ictr[l] = 10 + l;
            iltrb[l] = 15 + l; icls[l] = 20 + l; ipos[l] = 25 + l;
        }
    }

    fcos_work_kernel<<<GRID, 256>>>(
        (const float*)d_in[iconf[0]], (const float*)d_in[iconf[1]],
        (const float*)d_in[iconf[2]], (const float*)d_in[iconf[3]],
        (const float*)d_in[iconf[4]],
        (const float*)d_in[iloc[0]],  (const float*)d_in[iloc[1]],
        (const float*)d_in[iloc[2]],  (const float*)d_in[iloc[3]],
        (const float*)d_in[iloc[4]],
        (const float*)d_in[ictr[0]],  (const float*)d_in[ictr[1]],
        (const float*)d_in[ictr[2]],  (const float*)d_in[ictr[3]],
        (const float*)d_in[ictr[4]],
        (const float*)d_in[iltrb[0]], (const float*)d_in[iltrb[1]],
        (const float*)d_in[iltrb[2]], (const float*)d_in[iltrb[3]],
        (const float*)d_in[iltrb[4]],
        (const int*)d_in[icls[0]], (const int*)d_in[icls[1]],
        (const int*)d_in[icls[2]], (const int*)d_in[icls[3]],
        (const int*)d_in[icls[4]],
        (const int*)d_in[ipos[0]], (const int*)d_in[ipos[1]],
        (const int*)d_in[ipos[2]], (const int*)d_in[ipos[3]],
        (const int*)d_in[ipos[4]],
        (float*)d_out);
}

// round 15
// speedup vs baseline: 1.5126x; 1.0440x over previous
#include <cuda_runtime.h>

// ---------------------------------------------------------------------------
// FCOS loss, 5 FPN levels, B=16, C=80 — persistent kernel, dynamic balancing.
// Each CTA is bound to one image (b = blockIdx.x % 16; 74 CTAs/image) and
// pulls focal tile indices from a per-image atomic work counter (self-
// balancing; next index prefetched under the current tile's compute).
// Focal sums accumulate in registers across the CTA's whole lifetime and are
// reduced+flushed ONCE. Pixel units: static stride, after the focal loop.
// Last CTA finalizes the scalar and resets all state (replay-deterministic).
// ---------------------------------------------------------------------------

#define NB 16          // batch
#define NC 80          // classes

// per-level HW
#define HW0 12800
#define HW1 3200
#define HW2 800
#define HW3 208
#define HW4 56

// per-level C*H*W in float4 units (C*HW/4)
#define CHWV0 256000
#define CHWV1 64000
#define CHWV2 16000
#define CHWV3 4160
#define CHWV4 1120

// focal tiling: 256 threads x 4 float4 per thread = 1024 vec4 per tile
#define BVEC 1024
#define BLK0 250   // ceil(256000/1024)
#define BLK1 63
#define BLK2 16
#define BLK3 5
#define BLK4 2
#define CB1 (BLK0)                 // 250
#define CB2 (CB1+BLK1)             // 313
#define CB3 (CB2+BLK2)             // 329
#define CB4 (CB3+BLK3)             // 334
#define NBLKX (CB4+BLK4)           // 336 focal tiles per image

// pixel work: pixels per level across batch (B*HW), cumulative
#define P0 (NB*HW0)                // 204800
#define P1 (P0 + NB*HW1)           // 256000
#define P2 (P1 + NB*HW2)           // 268800
#define P3 (P2 + NB*HW3)           // 272128
#define P4 (P3 + NB*HW4)           // 273024
#define PIXU ((P4 + 255) / 256)    // 1067 pixel units

#define GRID 1184                  // 148 SMs x 8 CTAs; 74 CTAs per image

// 0.75 * ln(2): folds -(1-ALPHA) and the log2->ln conversion
#define NEG_SCALE (-0.519860385f)

// accumulators + work counters (zero at load, reset to zero by last CTA)
__device__ float    g_conf[NB];
__device__ float    g_loc[NB];
__device__ float    g_ctr[NB];
__device__ int      g_npos[NB];
__device__ unsigned g_bx[NB * 32];   // per-image tile counter, 128B stride
__device__ unsigned g_count;

__device__ __forceinline__ float clipp(float p) {
    return fminf(fmaxf(p, 1e-8f), 0.99999999f);
}

// ---------------------------------------------------------------------------
__global__ __launch_bounds__(256) void fcos_work_kernel(
    const float* __restrict__ c0, const float* __restrict__ c1,
    const float* __restrict__ c2, const float* __restrict__ c3,
    const float* __restrict__ c4,
    const float* __restrict__ l0, const float* __restrict__ l1,
    const float* __restrict__ l2, const float* __restrict__ l3,
    const float* __restrict__ l4,
    const float* __restrict__ ce0, const float* __restrict__ ce1,
    const float* __restrict__ ce2, const float* __restrict__ ce3,
    const float* __restrict__ ce4,
    const float* __restrict__ t0, const float* __restrict__ t1,
    const float* __restrict__ t2, const float* __restrict__ t3,
    const float* __restrict__ t4,
    const int* __restrict__ k0, const int* __restrict__ k1,
    const int* __restrict__ k2, const int* __restrict__ k3,
    const int* __restrict__ k4,
    const int* __restrict__ m0, const int* __restrict__ m1,
    const int* __restrict__ m2, const int* __restrict__ m3,
    const int* __restrict__ m4,
    float* __restrict__ out)
{
    __shared__ float s_conf[NB], s_loc[NB], s_ctr[NB];
    __shared__ int   s_np[NB];
    __shared__ unsigned s_bx;
    __shared__ int   s_last;

    const int cta  = blockIdx.x;
    const int tid  = threadIdx.x;
    const int b    = cta & (NB - 1);        // image bound to this CTA
    unsigned* __restrict__ ctr_bx = &g_bx[b * 32];

    if (tid < NB) {
        s_conf[tid] = 0.0f; s_loc[tid] = 0.0f; s_ctr[tid] = 0.0f; s_np[tid] = 0;
    }

    // =================== focal streaming, dynamic tiles ===================
    // Per-thread accumulator of p^2*log2(1-p) over all tiles this CTA takes.
    float acc = 0.0f;

    if (tid == 0) s_bx = atomicAdd(ctr_bx, 1u);
    __syncthreads();
    unsigned bx = s_bx;

    while (bx < NBLKX) {
        __syncthreads();                          // all threads captured s_bx
        if (tid == 0) s_bx = atomicAdd(ctr_bx, 1u);  // prefetch next tile id

        const float4* __restrict__ cp;
        int chwv, inner;
        if (bx < CB1)      { cp = (const float4*)c0; chwv = CHWV0; inner = bx;       }
        else if (bx < CB2) { cp = (const float4*)c1; chwv = CHWV1; inner = bx - CB1; }
        else if (bx < CB3) { cp = (const float4*)c2; chwv = CHWV2; inner = bx - CB2; }
        else if (bx < CB4) { cp = (const float4*)c3; chwv = CHWV3; inner = bx - CB3; }
        else               { cp = (const float4*)c4; chwv = CHWV4; inner = bx - CB4; }

        cp += (long)b * chwv;
        const int base = inner * BVEC + tid;

        // (No in-stream clipping: p in [0,1); clip effect < 1e-16.)
        if (inner * BVEC + BVEC <= chwv) {
            float4 r[4];
            #pragma unroll
            for (int k = 0; k < 4; k++) r[k] = __ldg(cp + base + k * 256);
            #pragma unroll
            for (int k = 0; k < 4; k++) {
                float4 p = r[k];
                acc += p.x * p.x * __log2f(1.0f - p.x)
                     + p.y * p.y * __log2f(1.0f - p.y)
                     + p.z * p.z * __log2f(1.0f - p.z)
                     + p.w * p.w * __log2f(1.0f - p.w);
            }
        } else {
            #pragma unroll
            for (int k = 0; k < 4; k++) {
                int v = base + k * 256;
                if (v < chwv) {
                    float4 p = __ldg(cp + v);
                    acc += p.x * p.x * __log2f(1.0f - p.x)
                         + p.y * p.y * __log2f(1.0f - p.y)
                         + p.z * p.z * __log2f(1.0f - p.z)
                         + p.w * p.w * __log2f(1.0f - p.w);
                }
            }
        }

        __syncthreads();                          // new s_bx visible
        bx = s_bx;
    }

    // ==================== sparse positive-pixel unit ====================
    for (int pu = (GRID - 1) - cta; pu < PIXU; pu += GRID) {
        const int id = pu * 256 + tid;
        if (id < P4) {
            const float *conf, *loc, *ctr, *ltrb;
            const int *cls, *pos;
            int HW, i;
            if (id < P0)      { conf=c0; loc=l0; ctr=ce0; ltrb=t0; cls=k0; pos=m0; HW=HW0; i=id;    }
            else if (id < P1) { conf=c1; loc=l1; ctr=ce1; ltrb=t1; cls=k1; pos=m1; HW=HW1; i=id-P0; }
            else if (id < P2) { conf=c2; loc=l2; ctr=ce2; ltrb=t2; cls=k2; pos=m2; HW=HW2; i=id-P1; }
            else if (id < P3) { conf=c3; loc=l3; ctr=ce3; ltrb=t3; cls=k3; pos=m3; HW=HW3; i=id-P2; }
            else              { conf=c4; loc=l4; ctr=ce4; ltrb=t4; cls=k4; pos=m4; HW=HW4; i=id-P3; }

            const int bb  = i / HW;
            const int pix = i - bb * HW;
            const long pbase = (long)bb * HW + pix;

            if (pos[pbase] == 0) {
                // focal correction at (bb, cls, pix): pos - neg
                const int c = cls[pbase];
                float p = clipp(conf[((long)bb * NC + c) * HW + pix]);
                float q = 1.0f - p;
                float corr = -0.25f * q * q * __logf(p) + 0.75f * p * p * __logf(q);

                // IoU loss
                const long o = (long)bb * 4 * HW + pix;
                float lp = loc[o]           * 32.0f;
                float tp = loc[o + HW]      * 32.0f;
                float rp = loc[o + 2 * HW]  * 32.0f;
                float bp = loc[o + 3 * HW]  * 32.0f;
                float lt = ltrb[o]          * 32.0f;
                float tt = ltrb[o + HW]     * 32.0f;
                float rt = ltrb[o + 2 * HW] * 32.0f;
                float bt = ltrb[o + 3 * HW] * 32.0f;

                float iw = fmaxf(fminf(lp, lt) + fminf(rp, rt), 0.0f);
                float ih = fmaxf(fminf(tp, tt) + fminf(bp, bt), 0.0f);
                float inter  = iw * ih;
                float area_p = fmaxf(lp + rp, 0.0f) * fmaxf(tp + bp, 0.0f);
                float area_t = (lt + rt) * (tt + bt);
                float iou = inter / (area_p + area_t - inter + 1e-6f);
                float loss_l = -__logf(iou + 1e-6f);

                // centerness BCE
                float ctr_t = sqrtf((fminf(lt, rt) / (fmaxf(lt, rt) + 1e-6f)) *
                                    (fminf(tt, bt) / (fmaxf(tt, bt) + 1e-6f)));
                float cp2 = ctr[pbase];
                cp2 = fminf(fmaxf(cp2, 1e-8f), 1.0f - 1e-8f);
                float bce = -(ctr_t * __logf(cp2) + (1.0f - ctr_t) * __logf(1.0f - cp2));

                atomicAdd(&s_conf[bb], corr);
                atomicAdd(&s_loc[bb],  loss_l);
                atomicAdd(&s_ctr[bb],  bce);
                atomicAdd(&s_np[bb],   1);
            }
        }
    }

    // ======= reduce the CTA's focal accumulator once, into smem =======
    acc *= NEG_SCALE;
    #pragma unroll
    for (int o = 16; o > 0; o >>= 1)
        acc += __shfl_down_sync(0xffffffffu, acc, o);
    if ((tid & 31) == 0)
        atomicAdd(&s_conf[b], acc);

    // ============ flush CTA partials once, then completion ============
    __syncthreads();
    if (tid < NB) {
        if (s_conf[tid] != 0.0f) atomicAdd(&g_conf[tid], s_conf[tid]);
        if (s_loc[tid]  != 0.0f) atomicAdd(&g_loc[tid],  s_loc[tid]);
        if (s_ctr[tid]  != 0.0f) atomicAdd(&g_ctr[tid],  s_ctr[tid]);
        if (s_np[tid])           atomicAdd(&g_npos[tid], s_np[tid]);
    }
    if ((tid >> 5) == 0)
        __threadfence();   // release: flushing warp only (1 MEMBAR/CTA)
    __syncthreads();
    if (tid == 0)
        s_last = (atomicAdd(&g_count, 1u) == (unsigned)(GRID - 1));
    __syncthreads();

    if (s_last && tid < 32) {
        __threadfence();   // acquire: all prior releases are now visible
        volatile float* vconf = g_conf;
        volatile float* vloc  = g_loc;
        volatile float* vctr  = g_ctr;
        volatile int*   vnp   = g_npos;

        float v = 0.0f;
        if (tid < NB) {
            float lc = vconf[tid], ll = vloc[tid], lctr = vctr[tid];
            int   np = vnp[tid];
            float pf = (float)np;
            v = (np > 0) ? (lctr + (lc + ll) / fmaxf(pf, 1.0f))
                         : (lctr + lc + ll);
        }
        #pragma unroll
        for (int o = 16; o > 0; o >>= 1)
            v += __shfl_down_sync(0xffffffffu, v, o);
        if (tid == 0) out[0] = v * (1.0f / (float)NB);

        // reset ALL state for the next invocation / graph replay
        if (tid < NB) {
            vconf[tid] = 0.0f; vloc[tid] = 0.0f; vctr[tid] = 0.0f; vnp[tid] = 0;
            g_bx[tid * 32] = 0u;
        }
        __threadfence();
        if (tid == 0) g_count = 0u;
    }
}

// ---------------------------------------------------------------------------
extern "C" void kernel_launch(void* const* d_in, const int* in_sizes, int n_in,
                              void* d_out, int out_size)
{
    (void)n_in; (void)out_size;

    // Runtime input-order detection.
    // Per-level order:    in_sizes[1] = 16*4*12800 = 819200   (loc0)
    // Type-grouped order: in_sizes[1] = 16*80*3200 = 4096000  (conf1)
    int iconf[5], iloc[5], ictr[5], iltrb[5], icls[5], ipos[5];
    if (in_sizes[1] == 16 * 4 * 12800) {
        for (int l = 0; l < 5; l++) {
            iconf[l] = 6 * l + 0; iloc[l] = 6 * l + 1; ictr[l] = 6 * l + 2;
            iltrb[l] = 6 * l + 3; icls[l] = 6 * l + 4; ipos[l] = 6 * l + 5;
        }
    } else {
        for (int l = 0; l < 5; l++) {
            iconf[l] = l; iloc[l] = 5 + l; ictr[l] = 10 + l;
            iltrb[l] = 15 + l; icls[l] = 20 + l; ipos[l] = 25 + l;
        }
    }

    fcos_work_kernel<<<GRID, 256>>>(
        (const float*)d_in[iconf[0]], (const float*)d_in[iconf[1]],
        (const float*)d_in[iconf[2]], (const float*)d_in[iconf[3]],
        (const float*)d_in[iconf[4]],
        (const float*)d_in[iloc[0]],  (const float*)d_in[iloc[1]],
        (const float*)d_in[iloc[2]],  (const float*)d_in[iloc[3]],
        (const float*)d_in[iloc[4]],
        (const float*)d_in[ictr[0]],  (const float*)d_in[ictr[1]],
        (const float*)d_in[ictr[2]],  (const float*)d_in[ictr[3]],
        (const float*)d_in[ictr[4]],
        (const float*)d_in[iltrb[0]], (const float*)d_in[iltrb[1]],
        (const float*)d_in[iltrb[2]], (const float*)d_in[iltrb[3]],
        (const float*)d_in[iltrb[4]],
        (const int*)d_in[icls[0]], (const int*)d_in[icls[1]],
        (const int*)d_in[icls[2]], (const int*)d_in[icls[3]],
        (const int*)d_in[icls[4]],
        (const int*)d_in[ipos[0]], (const int*)d_in[ipos[1]],
        (const int*)d_in[ipos[2]], (const int*)d_in[ipos[3]],
        (const int*)d_in[ipos[4]],
        (float*)d_out);
}